// round 3
// baseline (speedup 1.0000x reference)
#include <cuda_runtime.h>
#include <cuda_bf16.h>
#include <math.h>
#include <mma.h>

using namespace nvcuda;

#define N_NODES   100000
#define MAX_E     3300000
#define D         128
#define D_FF      256
#define N_CLASSES 26
#define N_GRAPHS  512
#define SCAN_BLK  1024

// ---------------- scratch (static __device__ — allocation-guard safe) -------
__device__ float g_h   [(size_t)N_NODES * D];
__device__ float g_act [(size_t)N_NODES * D];
__device__ int   g_edeg[N_NODES];
__device__ float g_dinv[N_NODES];
__device__ int   g_off [N_NODES + 1];
__device__ int   g_fill[N_NODES];
__device__ int   g_bsum[256];
__device__ int   g_csr_src[MAX_E];
__device__ float g_csr_w  [MAX_E];
__device__ int   g_batch[N_NODES];
__device__ float g_psum[N_GRAPHS * D];
__device__ int   g_cnt [N_GRAPHS];
__device__ int   g_is64;

// ---------------- helpers ---------------------------------------------------
__device__ __forceinline__ long long load_index(const void* p, long long pos, int is64) {
    if (is64) return ((const long long*)p)[pos];
    return (long long)((const int*)p)[pos];
}

__device__ __forceinline__ void red_add_v4(float* addr, float4 v) {
    asm volatile("red.global.add.v4.f32 [%0], {%1, %2, %3, %4};"
                 :: "l"(addr), "f"(v.x), "f"(v.y), "f"(v.z), "f"(v.w)
                 : "memory");
}

__device__ __forceinline__ float to_tf32(float x) {
    float r;
    asm("cvt.rna.tf32.f32 %0, %1;" : "=f"(r) : "f"(x));
    return r;
}

// ---------------- setup kernels ---------------------------------------------
__global__ void detect_kernel(const int* ei) {
    if (blockIdx.x == 0 && threadIdx.x == 0) {
        int all0 = 1;
        #pragma unroll
        for (int i = 1; i < 64; i += 2) all0 &= (ei[i] == 0);
        g_is64 = all0;
    }
}

__global__ void init_kernel(int n) {
    int i = blockIdx.x * blockDim.x + threadIdx.x;
    if (i < n) g_edeg[i] = 0;
    if (i < N_GRAPHS * D) g_psum[i] = 0.f;
    if (i < N_GRAPHS) g_cnt[i] = 0;
}

__global__ void degree_kernel(const void* ei, int E) {
    int is64 = g_is64;
    for (long long e = blockIdx.x * (long long)blockDim.x + threadIdx.x;
         e < E; e += (long long)gridDim.x * blockDim.x) {
        long long d = load_index(ei, (long long)E + e, is64);
        atomicAdd(&g_edeg[d], 1);
    }
}

// exclusive scan phase A (+ fused dinv)
__global__ void scanA_kernel(int n) {
    __shared__ int ssum[256];
    int b = blockIdx.x, t = threadIdx.x;
    int base = b * SCAN_BLK + t * 4;
    int v[4];
    #pragma unroll
    for (int j = 0; j < 4; j++) {
        int idx = base + j;
        v[j] = (idx < n) ? g_edeg[idx] : 0;
        if (idx < n) g_dinv[idx] = rsqrtf((float)(v[j] + 1));
    }
    int tot = v[0] + v[1] + v[2] + v[3];
    ssum[t] = tot;
    __syncthreads();
    #pragma unroll
    for (int ofs = 1; ofs < 256; ofs <<= 1) {
        int val = (t >= ofs) ? ssum[t - ofs] : 0;
        __syncthreads();
        ssum[t] += val;
        __syncthreads();
    }
    int excl = ssum[t] - tot;
    int run = excl;
    #pragma unroll
    for (int j = 0; j < 4; j++) {
        int idx = base + j;
        if (idx < n) g_off[idx] = run;
        run += v[j];
    }
    if (t == 255) g_bsum[b] = ssum[255];
}

__global__ void scanB_kernel(int nb, int n) {
    if (threadIdx.x == 0 && blockIdx.x == 0) {
        int run = 0;
        for (int b = 0; b < nb; b++) {
            int t = g_bsum[b];
            g_bsum[b] = run;
            run += t;
        }
        g_off[n] = run;
    }
}

__global__ void scanC_kernel(int n) {
    int i = blockIdx.x * blockDim.x + threadIdx.x;
    if (i < n) {
        int o = g_off[i] + g_bsum[i / SCAN_BLK];
        g_off[i] = o;
        g_fill[i] = o;
    }
}

__global__ void fill_kernel(const void* ei, int E) {
    int is64 = g_is64;
    for (long long e = blockIdx.x * (long long)blockDim.x + threadIdx.x;
         e < E; e += (long long)gridDim.x * blockDim.x) {
        long long s = load_index(ei, e, is64);
        long long d = load_index(ei, (long long)E + e, is64);
        int pos = atomicAdd(&g_fill[d], 1);
        g_csr_src[pos] = (int)s;
        g_csr_w[pos] = g_dinv[s] * g_dinv[d];
    }
}

__global__ void batch_kernel(const void* batch, int n) {
    int is64 = g_is64;
    int i = blockIdx.x * blockDim.x + threadIdx.x;
    if (i < n) {
        int g = (int)load_index(batch, i, is64);
        g_batch[i] = g;
        atomicAdd(&g_cnt[g], 1);
    }
}

// ---------------- TF32 tensor-core GEMM: H = X @ W --------------------------
// 2-term tf32 split for fp32-grade accuracy: x*w ~= x1*w1 + x1*w2 + x2*w1.
// Block: 64 rows x 128 cols, 256 threads (8 warps: 4 row-groups x 2 col-groups).
#define W_LD 132
#define A_LD 136
__global__ void gcn_gemm_tc_kernel(const float* __restrict__ Xext,
                                   const float* __restrict__ W,
                                   int n, int use_x) {
    extern __shared__ float smem[];
    float* Ws1 = smem;                       // 128 x W_LD
    float* Ws2 = Ws1 + 128 * W_LD;           // 128 x W_LD
    float* As1 = Ws2 + 128 * W_LD;           // 64 x A_LD
    float* As2 = As1 + 64 * A_LD;            // 64 x A_LD

    const float* X = use_x ? Xext : g_act;
    int row0 = blockIdx.x * 64;
    int t = threadIdx.x;

    // load + split W (128x128)
    for (int i = t; i < 128 * 32; i += 256) {
        int r = i >> 5, c4 = (i & 31) << 2;
        float4 w = ((const float4*)(W + r * D))[c4 >> 2];
        float* p1 = Ws1 + r * W_LD + c4;
        float* p2 = Ws2 + r * W_LD + c4;
        float h;
        h = to_tf32(w.x); p1[0] = h; p2[0] = to_tf32(w.x - h);
        h = to_tf32(w.y); p1[1] = h; p2[1] = to_tf32(w.y - h);
        h = to_tf32(w.z); p1[2] = h; p2[2] = to_tf32(w.z - h);
        h = to_tf32(w.w); p1[3] = h; p2[3] = to_tf32(w.w - h);
    }

    // load + split A tile (64x128), zero-pad invalid rows
    for (int i = t; i < 64 * 32; i += 256) {
        int r = i >> 5, c4 = (i & 31) << 2;
        float* p1 = As1 + r * A_LD + c4;
        float* p2 = As2 + r * A_LD + c4;
        if (row0 + r < n) {
            float4 a = ((const float4*)(X + (size_t)(row0 + r) * D))[c4 >> 2];
            float h;
            h = to_tf32(a.x); p1[0] = h; p2[0] = to_tf32(a.x - h);
            h = to_tf32(a.y); p1[1] = h; p2[1] = to_tf32(a.y - h);
            h = to_tf32(a.z); p1[2] = h; p2[2] = to_tf32(a.z - h);
            h = to_tf32(a.w); p1[3] = h; p2[3] = to_tf32(a.w - h);
        } else {
            p1[0] = p1[1] = p1[2] = p1[3] = 0.f;
            p2[0] = p2[1] = p2[2] = p2[3] = 0.f;
        }
    }
    __syncthreads();

    int warp = t >> 5;
    int wrow = warp & 3;           // 0..3 : 16-row group
    int wcol = warp >> 2;          // 0..1 : 64-col group

    wmma::fragment<wmma::accumulator, 16, 16, 8, float> acc[4];
    #pragma unroll
    for (int j = 0; j < 4; j++) wmma::fill_fragment(acc[j], 0.f);

    const float* arow1 = As1 + wrow * 16 * A_LD;
    const float* arow2 = As2 + wrow * 16 * A_LD;

    #pragma unroll 1
    for (int k0 = 0; k0 < 128; k0 += 8) {
        wmma::fragment<wmma::matrix_a, 16, 16, 8, wmma::precision::tf32, wmma::row_major> a1, a2;
        wmma::load_matrix_sync(a1, arow1 + k0, A_LD);
        wmma::load_matrix_sync(a2, arow2 + k0, A_LD);
        #pragma unroll
        for (int nc = 0; nc < 4; nc++) {
            int ncol = wcol * 64 + nc * 16;
            wmma::fragment<wmma::matrix_b, 16, 16, 8, wmma::precision::tf32, wmma::row_major> b1, b2;
            wmma::load_matrix_sync(b1, Ws1 + k0 * W_LD + ncol, W_LD);
            wmma::load_matrix_sync(b2, Ws2 + k0 * W_LD + ncol, W_LD);
            wmma::mma_sync(acc[nc], a1, b1, acc[nc]);
            wmma::mma_sync(acc[nc], a1, b2, acc[nc]);
            wmma::mma_sync(acc[nc], a2, b1, acc[nc]);
        }
    }

    int rbase = row0 + wrow * 16;
    if (rbase < n) {   // n % 16 == 0 -> fragment fully valid
        #pragma unroll
        for (int nc = 0; nc < 4; nc++) {
            int ncol = wcol * 64 + nc * 16;
            wmma::store_matrix_sync(g_h + (size_t)rbase * D + ncol, acc[nc], D,
                                    wmma::mem_row_major);
        }
    }
}

// ---------------- gather: warp per node, fused bias+relu (+pool) ------------
__global__ void gather_kernel(const float* __restrict__ bias, int n, int do_pool) {
    int gwarp = (blockIdx.x * blockDim.x + threadIdx.x) >> 5;
    if (gwarp >= n) return;
    int lane = threadIdx.x & 31;
    int nd = gwarp;

    const float4* hp = (const float4*)g_h;
    float dv = g_dinv[nd];
    float d2 = dv * dv;
    float4 acc = hp[(size_t)nd * 32 + lane];
    acc.x *= d2; acc.y *= d2; acc.z *= d2; acc.w *= d2;

    int beg = g_off[nd];
    int end = g_off[nd + 1];
    int e = beg;
    for (; e + 1 < end; e += 2) {
        int   s0 = __ldg(&g_csr_src[e]);
        int   s1 = __ldg(&g_csr_src[e + 1]);
        float w0 = __ldg(&g_csr_w[e]);
        float w1 = __ldg(&g_csr_w[e + 1]);
        float4 v0 = hp[(size_t)s0 * 32 + lane];
        float4 v1 = hp[(size_t)s1 * 32 + lane];
        acc.x = fmaf(w0, v0.x, acc.x); acc.y = fmaf(w0, v0.y, acc.y);
        acc.z = fmaf(w0, v0.z, acc.z); acc.w = fmaf(w0, v0.w, acc.w);
        acc.x = fmaf(w1, v1.x, acc.x); acc.y = fmaf(w1, v1.y, acc.y);
        acc.z = fmaf(w1, v1.z, acc.z); acc.w = fmaf(w1, v1.w, acc.w);
    }
    if (e < end) {
        int   s = __ldg(&g_csr_src[e]);
        float w = __ldg(&g_csr_w[e]);
        float4 v = hp[(size_t)s * 32 + lane];
        acc.x = fmaf(w, v.x, acc.x); acc.y = fmaf(w, v.y, acc.y);
        acc.z = fmaf(w, v.z, acc.z); acc.w = fmaf(w, v.w, acc.w);
    }

    float4 bb = ((const float4*)bias)[lane];
    acc.x = fmaxf(acc.x + bb.x, 0.f);
    acc.y = fmaxf(acc.y + bb.y, 0.f);
    acc.z = fmaxf(acc.z + bb.z, 0.f);
    acc.w = fmaxf(acc.w + bb.w, 0.f);

    if (do_pool) {
        int g = g_batch[nd];
        red_add_v4(g_psum + (size_t)g * D + lane * 4, acc);
    } else {
        ((float4*)g_act)[(size_t)nd * 32 + lane] = acc;
    }
}

// ---------------- fused MLP head ---------------------------------------------
__global__ void fc_kernel(const float* __restrict__ Wfc, const float* __restrict__ bfc,
                          const float* __restrict__ Wfc2, const float* __restrict__ bfc2,
                          float* __restrict__ out) {
    __shared__ float p[D];
    __shared__ float h1[D_FF];
    int g = blockIdx.x;
    int t = threadIdx.x;

    int c = g_cnt[g]; if (c < 1) c = 1;
    float inv = 1.f / (float)c;
    if (t < D) p[t] = g_psum[g * D + t] * inv;
    __syncthreads();

    float s = bfc[t];
    #pragma unroll 4
    for (int k = 0; k < D; k++) s = fmaf(p[k], Wfc[k * D_FF + t], s);
    h1[t] = fmaxf(s, 0.f);
    __syncthreads();

    if (t < N_CLASSES) {
        float s2 = bfc2[t];
        #pragma unroll 4
        for (int k = 0; k < D_FF; k++) s2 = fmaf(h1[k], Wfc2[k * N_CLASSES + t], s2);
        out[g * N_CLASSES + t] = s2;
    }
}

// ---------------- launch -----------------------------------------------------
extern "C" void kernel_launch(void* const* d_in, const int* in_sizes, int n_in,
                              void* d_out, int out_size) {
    const float* x    = (const float*)d_in[0];
    const void*  ei   = d_in[1];
    const void*  batch= d_in[2];
    const float* W1   = (const float*)d_in[3];
    const float* b1   = (const float*)d_in[4];
    const float* W2   = (const float*)d_in[5];
    const float* b2   = (const float*)d_in[6];
    const float* W3   = (const float*)d_in[7];
    const float* b3   = (const float*)d_in[8];
    const float* Wfc  = (const float*)d_in[9];
    const float* bfc  = (const float*)d_in[10];
    const float* Wfc2 = (const float*)d_in[11];
    const float* bfc2 = (const float*)d_in[12];
    float* out = (float*)d_out;

    int n = in_sizes[0] / D;
    int E = in_sizes[1] / 2;

    const int GEMM_SMEM = (2 * 128 * W_LD + 2 * 64 * A_LD) * 4;   // 204800 B
    static bool attr_set = false;
    if (!attr_set) {
        cudaFuncSetAttribute(gcn_gemm_tc_kernel,
                             cudaFuncAttributeMaxDynamicSharedMemorySize, GEMM_SMEM);
        attr_set = true;
    }

    // ---- one-time setup ----
    detect_kernel<<<1, 32>>>((const int*)ei);
    init_kernel<<<(n + 255) / 256, 256>>>(n);
    degree_kernel<<<2048, 256>>>(ei, E);
    int nb = (n + SCAN_BLK - 1) / SCAN_BLK;
    scanA_kernel<<<nb, 256>>>(n);
    scanB_kernel<<<1, 32>>>(nb, n);
    scanC_kernel<<<(n + 255) / 256, 256>>>(n);
    fill_kernel<<<2048, 256>>>(ei, E);
    batch_kernel<<<(n + 255) / 256, 256>>>(batch, n);

    // ---- layers ----
    int gemm_blocks = (n + 63) / 64;
    int gather_blocks = (n * 32 + 255) / 256;

    gcn_gemm_tc_kernel<<<gemm_blocks, 256, GEMM_SMEM>>>(x, W1, n, 1);
    gather_kernel<<<gather_blocks, 256>>>(b1, n, 0);

    gcn_gemm_tc_kernel<<<gemm_blocks, 256, GEMM_SMEM>>>(x, W2, n, 0);
    gather_kernel<<<gather_blocks, 256>>>(b2, n, 0);

    gcn_gemm_tc_kernel<<<gemm_blocks, 256, GEMM_SMEM>>>(x, W3, n, 0);
    gather_kernel<<<gather_blocks, 256>>>(b3, n, 1);

    fc_kernel<<<N_GRAPHS, D_FF>>>(Wfc, bfc, Wfc2, bfc2, out);
}

// round 4
// speedup vs baseline: 1.4626x; 1.4626x over previous
#include <cuda_runtime.h>
#include <cuda_fp16.h>
#include <math.h>

#define N_NODES   100000
#define MAX_E     3300000
#define D         128
#define D_FF      256
#define N_CLASSES 26
#define N_GRAPHS  512
#define SCAN_BLK  1024

// ---------------- scratch (static __device__ — allocation-guard safe) -------
__device__ __half g_h  [(size_t)N_NODES * D];    // fp16 messages
__device__ float  g_act[(size_t)N_NODES * D];    // fp32 activations
__device__ int    g_edeg[N_NODES];
__device__ float  g_dinv[N_NODES];
__device__ int    g_off [N_NODES + 1];
__device__ int    g_fill[N_NODES];
__device__ int    g_bsum[256];
__device__ int2   g_csr [MAX_E];                 // (src, weight-bits)
__device__ int    g_batch[N_NODES];
__device__ float  g_psum[N_GRAPHS * D];
__device__ int    g_cnt [N_GRAPHS];
__device__ int    g_is64;

// ---------------- helpers ---------------------------------------------------
__device__ __forceinline__ long long load_index(const void* p, long long pos, int is64) {
    if (is64) return ((const long long*)p)[pos];
    return (long long)((const int*)p)[pos];
}

__device__ __forceinline__ void red_add_v4(float* addr, float4 v) {
    asm volatile("red.global.add.v4.f32 [%0], {%1, %2, %3, %4};"
                 :: "l"(addr), "f"(v.x), "f"(v.y), "f"(v.z), "f"(v.w)
                 : "memory");
}

// unpack 4 halves (uint2) and fma into acc
__device__ __forceinline__ void fma4_h(float4& acc, uint2 hv, float w) {
    __half2 h01 = *(__half2*)&hv.x;
    __half2 h23 = *(__half2*)&hv.y;
    float2 f01 = __half22float2(h01);
    float2 f23 = __half22float2(h23);
    acc.x = fmaf(w, f01.x, acc.x);
    acc.y = fmaf(w, f01.y, acc.y);
    acc.z = fmaf(w, f23.x, acc.z);
    acc.w = fmaf(w, f23.y, acc.w);
}

// ---------------- setup kernels ---------------------------------------------
__global__ void detect_kernel(const int* ei) {
    if (blockIdx.x == 0 && threadIdx.x == 0) {
        int all0 = 1;
        #pragma unroll
        for (int i = 1; i < 64; i += 2) all0 &= (ei[i] == 0);
        g_is64 = all0;
    }
}

__global__ void init_kernel(int n) {
    int i = blockIdx.x * blockDim.x + threadIdx.x;
    if (i < n) g_edeg[i] = 0;
    if (i < N_GRAPHS * D) g_psum[i] = 0.f;
    if (i < N_GRAPHS) g_cnt[i] = 0;
}

__global__ void degree_kernel(const void* ei, int E) {
    int is64 = g_is64;
    for (long long e = blockIdx.x * (long long)blockDim.x + threadIdx.x;
         e < E; e += (long long)gridDim.x * blockDim.x) {
        long long d = load_index(ei, (long long)E + e, is64);
        atomicAdd(&g_edeg[d], 1);
    }
}

// exclusive scan phase A (+ fused dinv)
__global__ void scanA_kernel(int n) {
    __shared__ int ssum[256];
    int b = blockIdx.x, t = threadIdx.x;
    int base = b * SCAN_BLK + t * 4;
    int v[4];
    #pragma unroll
    for (int j = 0; j < 4; j++) {
        int idx = base + j;
        v[j] = (idx < n) ? g_edeg[idx] : 0;
        if (idx < n) g_dinv[idx] = rsqrtf((float)(v[j] + 1));
    }
    int tot = v[0] + v[1] + v[2] + v[3];
    ssum[t] = tot;
    __syncthreads();
    #pragma unroll
    for (int ofs = 1; ofs < 256; ofs <<= 1) {
        int val = (t >= ofs) ? ssum[t - ofs] : 0;
        __syncthreads();
        ssum[t] += val;
        __syncthreads();
    }
    int excl = ssum[t] - tot;
    int run = excl;
    #pragma unroll
    for (int j = 0; j < 4; j++) {
        int idx = base + j;
        if (idx < n) g_off[idx] = run;
        run += v[j];
    }
    if (t == 255) g_bsum[b] = ssum[255];
}

__global__ void scanB_kernel(int nb, int n) {
    if (threadIdx.x == 0 && blockIdx.x == 0) {
        int run = 0;
        for (int b = 0; b < nb; b++) {
            int t = g_bsum[b];
            g_bsum[b] = run;
            run += t;
        }
        g_off[n] = run;
    }
}

// phase C: finalize offsets + fill ptrs + batch decode + graph counts
__global__ void scanC_kernel(const void* batch, int n) {
    int i = blockIdx.x * blockDim.x + threadIdx.x;
    if (i < n) {
        int o = g_off[i] + g_bsum[i / SCAN_BLK];
        g_off[i] = o;
        g_fill[i] = o;
        int g = (int)load_index(batch, i, g_is64);
        g_batch[i] = g;
        atomicAdd(&g_cnt[g], 1);
    }
}

__global__ void fill_kernel(const void* ei, int E) {
    int is64 = g_is64;
    for (long long e = blockIdx.x * (long long)blockDim.x + threadIdx.x;
         e < E; e += (long long)gridDim.x * blockDim.x) {
        long long s = load_index(ei, e, is64);
        long long d = load_index(ei, (long long)E + e, is64);
        int pos = atomicAdd(&g_fill[d], 1);
        float w = g_dinv[s] * g_dinv[d];
        g_csr[pos] = make_int2((int)s, __float_as_int(w));
    }
}

// ---------------- SIMT GEMM: H = X @ W, fp16 epilogue ------------------------
// Block: 64 rows x 128 cols, 256 threads, 4x8 per thread. (R2-proven core.)
__global__ void gcn_gemm_kernel(const float* __restrict__ Xext,
                                const float* __restrict__ W,
                                int n, int use_x) {
    extern __shared__ float smem[];
    float* Ws = smem;                 // 128*128
    float* Xs = smem + 128 * 128;     // 64*132
    const int XS_LD = 132;
    const float* X = use_x ? Xext : g_act;

    int row0 = blockIdx.x * 64;

    for (int i = threadIdx.x; i < 128 * 128 / 4; i += 256)
        ((float4*)Ws)[i] = ((const float4*)W)[i];

    int rows = n - row0; if (rows > 64) rows = 64;
    for (int i = threadIdx.x; i < rows * 32; i += 256) {
        int r = i >> 5, c4 = i & 31;
        ((float4*)(Xs + r * XS_LD))[c4] =
            ((const float4*)(X + (size_t)(row0 + r) * D))[c4];
    }
    __syncthreads();

    int ty = threadIdx.x >> 4;
    int tx = threadIdx.x & 15;

    float acc[4][8];
    #pragma unroll
    for (int i = 0; i < 4; i++)
        #pragma unroll
        for (int j = 0; j < 8; j++) acc[i][j] = 0.f;

    #pragma unroll 4
    for (int k = 0; k < 128; ++k) {
        const float* wrow = &Ws[k * 128 + tx * 8];
        float4 w0 = *(const float4*)(wrow);
        float4 w1 = *(const float4*)(wrow + 4);
        float wv[8] = {w0.x, w0.y, w0.z, w0.w, w1.x, w1.y, w1.z, w1.w};
        float a[4];
        #pragma unroll
        for (int i = 0; i < 4; i++) a[i] = Xs[(ty * 4 + i) * XS_LD + k];
        #pragma unroll
        for (int i = 0; i < 4; i++)
            #pragma unroll
            for (int j = 0; j < 8; j++) acc[i][j] = fmaf(a[i], wv[j], acc[i][j]);
    }

    #pragma unroll
    for (int i = 0; i < 4; i++) {
        int r = row0 + ty * 4 + i;
        if (r < n) {
            // convert 8 floats -> 8 halves (16 B) and store
            __half2 h0 = __floats2half2_rn(acc[i][0], acc[i][1]);
            __half2 h1 = __floats2half2_rn(acc[i][2], acc[i][3]);
            __half2 h2 = __floats2half2_rn(acc[i][4], acc[i][5]);
            __half2 h3 = __floats2half2_rn(acc[i][6], acc[i][7]);
            uint4 pack;
            pack.x = *(unsigned*)&h0; pack.y = *(unsigned*)&h1;
            pack.z = *(unsigned*)&h2; pack.w = *(unsigned*)&h3;
            *(uint4*)((char*)g_h + (size_t)r * 256 + tx * 16) = pack;
        }
    }
}

// ---------------- gather: warp per node, fp16 messages, fused epilogue ------
__global__ void gather_kernel(const float* __restrict__ bias, int n, int do_pool) {
    int gwarp = (blockIdx.x * blockDim.x + threadIdx.x) >> 5;
    if (gwarp >= n) return;
    int lane = threadIdx.x & 31;
    int nd = gwarp;

    const uint2* hp = (const uint2*)g_h;   // 4 halves per uint2, 32 per row
    float dv = g_dinv[nd];
    float d2 = dv * dv;

    float4 acc = make_float4(0.f, 0.f, 0.f, 0.f);
    fma4_h(acc, hp[(size_t)nd * 32 + lane], d2);   // self loop

    int beg = g_off[nd];
    int end = g_off[nd + 1];
    int e = beg;
    for (; e + 3 < end; e += 4) {
        int2 r0 = __ldg(&g_csr[e]);
        int2 r1 = __ldg(&g_csr[e + 1]);
        int2 r2 = __ldg(&g_csr[e + 2]);
        int2 r3 = __ldg(&g_csr[e + 3]);
        uint2 v0 = hp[(size_t)r0.x * 32 + lane];
        uint2 v1 = hp[(size_t)r1.x * 32 + lane];
        uint2 v2 = hp[(size_t)r2.x * 32 + lane];
        uint2 v3 = hp[(size_t)r3.x * 32 + lane];
        fma4_h(acc, v0, __int_as_float(r0.y));
        fma4_h(acc, v1, __int_as_float(r1.y));
        fma4_h(acc, v2, __int_as_float(r2.y));
        fma4_h(acc, v3, __int_as_float(r3.y));
    }
    for (; e < end; e++) {
        int2 r = __ldg(&g_csr[e]);
        fma4_h(acc, hp[(size_t)r.x * 32 + lane], __int_as_float(r.y));
    }

    float4 bb = ((const float4*)bias)[lane];
    acc.x = fmaxf(acc.x + bb.x, 0.f);
    acc.y = fmaxf(acc.y + bb.y, 0.f);
    acc.z = fmaxf(acc.z + bb.z, 0.f);
    acc.w = fmaxf(acc.w + bb.w, 0.f);

    if (do_pool) {
        int g = g_batch[nd];
        red_add_v4(g_psum + (size_t)g * D + lane * 4, acc);
    } else {
        ((float4*)g_act)[(size_t)nd * 32 + lane] = acc;
    }
}

// ---------------- fused MLP head ---------------------------------------------
__global__ void fc_kernel(const float* __restrict__ Wfc, const float* __restrict__ bfc,
                          const float* __restrict__ Wfc2, const float* __restrict__ bfc2,
                          float* __restrict__ out) {
    __shared__ float p[D];
    __shared__ float h1[D_FF];
    int g = blockIdx.x;
    int t = threadIdx.x;

    int c = g_cnt[g]; if (c < 1) c = 1;
    float inv = 1.f / (float)c;
    if (t < D) p[t] = g_psum[g * D + t] * inv;
    __syncthreads();

    float s = bfc[t];
    #pragma unroll 4
    for (int k = 0; k < D; k++) s = fmaf(p[k], Wfc[k * D_FF + t], s);
    h1[t] = fmaxf(s, 0.f);
    __syncthreads();

    if (t < N_CLASSES) {
        float s2 = bfc2[t];
        #pragma unroll 4
        for (int k = 0; k < D_FF; k++) s2 = fmaf(h1[k], Wfc2[k * N_CLASSES + t], s2);
        out[g * N_CLASSES + t] = s2;
    }
}

// ---------------- launch -----------------------------------------------------
extern "C" void kernel_launch(void* const* d_in, const int* in_sizes, int n_in,
                              void* d_out, int out_size) {
    const float* x    = (const float*)d_in[0];
    const void*  ei   = d_in[1];
    const void*  batch= d_in[2];
    const float* W1   = (const float*)d_in[3];
    const float* b1   = (const float*)d_in[4];
    const float* W2   = (const float*)d_in[5];
    const float* b2   = (const float*)d_in[6];
    const float* W3   = (const float*)d_in[7];
    const float* b3   = (const float*)d_in[8];
    const float* Wfc  = (const float*)d_in[9];
    const float* bfc  = (const float*)d_in[10];
    const float* Wfc2 = (const float*)d_in[11];
    const float* bfc2 = (const float*)d_in[12];
    float* out = (float*)d_out;

    int n = in_sizes[0] / D;
    int E = in_sizes[1] / 2;

    static bool attr_set = false;
    const int GEMM_SMEM = (128 * 128 + 64 * 132) * 4;
    if (!attr_set) {
        cudaFuncSetAttribute(gcn_gemm_kernel,
                             cudaFuncAttributeMaxDynamicSharedMemorySize, GEMM_SMEM);
        attr_set = true;
    }

    // ---- one-time setup ----
    detect_kernel<<<1, 32>>>((const int*)ei);
    init_kernel<<<(n + 255) / 256, 256>>>(n);
    degree_kernel<<<2048, 256>>>(ei, E);
    int nb = (n + SCAN_BLK - 1) / SCAN_BLK;
    scanA_kernel<<<nb, 256>>>(n);
    scanB_kernel<<<1, 32>>>(nb, n);
    scanC_kernel<<<(n + 255) / 256, 256>>>(batch, n);
    fill_kernel<<<2048, 256>>>(ei, E);

    // ---- layers ----
    int gemm_blocks = (n + 63) / 64;
    int gather_blocks = (n * 32 + 255) / 256;

    gcn_gemm_kernel<<<gemm_blocks, 256, GEMM_SMEM>>>(x, W1, n, 1);
    gather_kernel<<<gather_blocks, 256>>>(b1, n, 0);

    gcn_gemm_kernel<<<gemm_blocks, 256, GEMM_SMEM>>>(x, W2, n, 0);
    gather_kernel<<<gather_blocks, 256>>>(b2, n, 0);

    gcn_gemm_kernel<<<gemm_blocks, 256, GEMM_SMEM>>>(x, W3, n, 0);
    gather_kernel<<<gather_blocks, 256>>>(b3, n, 1);

    fc_kernel<<<N_GRAPHS, D_FF>>>(Wfc, bfc, Wfc2, bfc2, out);
}

// round 5
// speedup vs baseline: 2.3619x; 1.6149x over previous
#include <cuda_runtime.h>
#include <cuda_fp16.h>
#include <math.h>
#include <mma.h>

using namespace nvcuda;

#define N_NODES   100000
#define MAX_E     3300000
#define D         128
#define D_FF      256
#define N_CLASSES 26
#define N_GRAPHS  512
#define SCAN_BLK  1024

// ---------------- scratch (static __device__ — allocation-guard safe) -------
__device__ __half g_h   [(size_t)N_NODES * D];   // fp16 messages (GEMM out)
__device__ __half g_acth[(size_t)N_NODES * D];   // fp16 activations (GEMM in)
__device__ int    g_edeg[N_NODES];
__device__ float  g_dinv[N_NODES];
__device__ int    g_off [N_NODES + 1];
__device__ int    g_fill[N_NODES];
__device__ int    g_bsum[256];
__device__ int2   g_csr [MAX_E];                 // (src, weight-bits)
__device__ int    g_batch[N_NODES];
__device__ float  g_psum[N_GRAPHS * D];
__device__ int    g_cnt [N_GRAPHS];
__device__ int    g_is64;

// ---------------- helpers ---------------------------------------------------
__device__ __forceinline__ long long load_index(const void* p, long long pos, int is64) {
    if (is64) return ((const long long*)p)[pos];
    return (long long)((const int*)p)[pos];
}

__device__ __forceinline__ void red_add_v4(float* addr, float4 v) {
    asm volatile("red.global.add.v4.f32 [%0], {%1, %2, %3, %4};"
                 :: "l"(addr), "f"(v.x), "f"(v.y), "f"(v.z), "f"(v.w)
                 : "memory");
}

__device__ __forceinline__ void fma4_h(float4& acc, uint2 hv, float w) {
    __half2 h01 = *(__half2*)&hv.x;
    __half2 h23 = *(__half2*)&hv.y;
    float2 f01 = __half22float2(h01);
    float2 f23 = __half22float2(h23);
    acc.x = fmaf(w, f01.x, acc.x);
    acc.y = fmaf(w, f01.y, acc.y);
    acc.z = fmaf(w, f23.x, acc.z);
    acc.w = fmaf(w, f23.y, acc.w);
}

__device__ __forceinline__ uint2 pack4_h(float4 v) {
    __half2 a = __floats2half2_rn(v.x, v.y);
    __half2 b = __floats2half2_rn(v.z, v.w);
    uint2 r;
    r.x = *(unsigned*)&a;
    r.y = *(unsigned*)&b;
    return r;
}

// ---------------- setup kernels ---------------------------------------------
__global__ void detect_kernel(const int* ei) {
    if (blockIdx.x == 0 && threadIdx.x == 0) {
        int all0 = 1;
        #pragma unroll
        for (int i = 1; i < 64; i += 2) all0 &= (ei[i] == 0);
        g_is64 = all0;
    }
}

__global__ void init_kernel(int n) {
    int i = blockIdx.x * blockDim.x + threadIdx.x;
    if (i < n) g_edeg[i] = 0;
    if (i < N_GRAPHS * D) g_psum[i] = 0.f;
    if (i < N_GRAPHS) g_cnt[i] = 0;
}

// x (fp32) -> g_acth (fp16); 8 elems per thread
__global__ void convert_x_kernel(const float* __restrict__ x, int n) {
    long long i = blockIdx.x * (long long)blockDim.x + threadIdx.x;
    long long total = (long long)n * 16;   // groups of 8
    if (i < total) {
        float4 a = ((const float4*)x)[i * 2];
        float4 b = ((const float4*)x)[i * 2 + 1];
        uint2 p0 = pack4_h(a);
        uint2 p1 = pack4_h(b);
        uint4 pk = make_uint4(p0.x, p0.y, p1.x, p1.y);
        ((uint4*)g_acth)[i] = pk;
    }
}

__global__ void degree_kernel(const void* ei, int E) {
    int is64 = g_is64;
    for (long long e = blockIdx.x * (long long)blockDim.x + threadIdx.x;
         e < E; e += (long long)gridDim.x * blockDim.x) {
        long long d = load_index(ei, (long long)E + e, is64);
        atomicAdd(&g_edeg[d], 1);
    }
}

__global__ void scanA_kernel(int n) {
    __shared__ int ssum[256];
    int b = blockIdx.x, t = threadIdx.x;
    int base = b * SCAN_BLK + t * 4;
    int v[4];
    #pragma unroll
    for (int j = 0; j < 4; j++) {
        int idx = base + j;
        v[j] = (idx < n) ? g_edeg[idx] : 0;
        if (idx < n) g_dinv[idx] = rsqrtf((float)(v[j] + 1));
    }
    int tot = v[0] + v[1] + v[2] + v[3];
    ssum[t] = tot;
    __syncthreads();
    #pragma unroll
    for (int ofs = 1; ofs < 256; ofs <<= 1) {
        int val = (t >= ofs) ? ssum[t - ofs] : 0;
        __syncthreads();
        ssum[t] += val;
        __syncthreads();
    }
    int excl = ssum[t] - tot;
    int run = excl;
    #pragma unroll
    for (int j = 0; j < 4; j++) {
        int idx = base + j;
        if (idx < n) g_off[idx] = run;
        run += v[j];
    }
    if (t == 255) g_bsum[b] = ssum[255];
}

__global__ void scanB_kernel(int nb, int n) {
    if (threadIdx.x == 0 && blockIdx.x == 0) {
        int run = 0;
        for (int b = 0; b < nb; b++) {
            int t = g_bsum[b];
            g_bsum[b] = run;
            run += t;
        }
        g_off[n] = run;
    }
}

__global__ void scanC_kernel(const void* batch, int n) {
    int i = blockIdx.x * blockDim.x + threadIdx.x;
    if (i < n) {
        int o = g_off[i] + g_bsum[i / SCAN_BLK];
        g_off[i] = o;
        g_fill[i] = o;
        int g = (int)load_index(batch, i, g_is64);
        g_batch[i] = g;
        atomicAdd(&g_cnt[g], 1);
    }
}

__global__ void fill_kernel(const void* ei, int E) {
    int is64 = g_is64;
    for (long long e = blockIdx.x * (long long)blockDim.x + threadIdx.x;
         e < E; e += (long long)gridDim.x * blockDim.x) {
        long long s = load_index(ei, e, is64);
        long long d = load_index(ei, (long long)E + e, is64);
        int pos = atomicAdd(&g_fill[d], 1);
        float w = g_dinv[s] * g_dinv[d];
        g_csr[pos] = make_int2((int)s, __float_as_int(w));
    }
}

// ---------------- fp16 tensor-core GEMM: g_h = g_acth @ fp16(W) --------------
// Block: 64 rows x 128 cols, 256 threads = 8 warps (4 row-groups x 2 col-groups).
// smem: W 128x136 half (34.8KB) + A 64x136 half (17.4KB); epilogue reuses W
// region as a 64x132 float tile.
#define AH_LD 136
#define C_LD  132
__global__ void gcn_gemm_tc16_kernel(const float* __restrict__ W, int n) {
    extern __shared__ char smc[];
    __half* Ws = (__half*)smc;                   // 128 x AH_LD
    __half* As = Ws + 128 * AH_LD;               // 64 x AH_LD
    float*  Cs = (float*)smc;                    // 64 x C_LD (epilogue, over Ws)

    int row0 = blockIdx.x * 64;
    int t = threadIdx.x;
    int rows = n - row0; if (rows > 64) rows = 64;

    // load + convert W (128x128 fp32 -> fp16)
    for (int i = t; i < 128 * 32; i += 256) {
        int r = i >> 5, c4 = (i & 31) << 2;
        float4 w = ((const float4*)(W + r * D))[c4 >> 2];
        *(uint2*)(Ws + r * AH_LD + c4) = pack4_h(w);
    }
    // load A tile (fp16, 8 halves = 16B per op)
    for (int i = t; i < 64 * 16; i += 256) {
        int r = i >> 4, c8 = (i & 15) << 3;
        uint4 v;
        if (r < rows)
            v = *(const uint4*)(g_acth + (size_t)(row0 + r) * D + c8);
        else
            v = make_uint4(0, 0, 0, 0);
        *(uint4*)(As + r * AH_LD + c8) = v;
    }
    __syncthreads();

    int warp = t >> 5;
    int wrow = warp & 3;          // 16-row group
    int wcol = warp >> 2;         // 64-col group

    wmma::fragment<wmma::accumulator, 16, 16, 16, float> acc[4];
    #pragma unroll
    for (int j = 0; j < 4; j++) wmma::fill_fragment(acc[j], 0.f);

    const __half* arow = As + wrow * 16 * AH_LD;
    #pragma unroll
    for (int k0 = 0; k0 < 128; k0 += 16) {
        wmma::fragment<wmma::matrix_a, 16, 16, 16, __half, wmma::row_major> af;
        wmma::load_matrix_sync(af, arow + k0, AH_LD);
        #pragma unroll
        for (int nc = 0; nc < 4; nc++) {
            int ncol = wcol * 64 + nc * 16;
            wmma::fragment<wmma::matrix_b, 16, 16, 16, __half, wmma::row_major> bf;
            wmma::load_matrix_sync(bf, Ws + k0 * AH_LD + ncol, AH_LD);
            wmma::mma_sync(acc[nc], af, bf, acc[nc]);
        }
    }
    __syncthreads();   // done reading Ws/As

    // accum -> smem fp32 tile
    #pragma unroll
    for (int nc = 0; nc < 4; nc++) {
        int ncol = wcol * 64 + nc * 16;
        wmma::store_matrix_sync(Cs + wrow * 16 * C_LD + ncol, acc[nc], C_LD,
                                wmma::mem_row_major);
    }
    __syncthreads();

    // smem fp32 -> global fp16 (packed 8 at a time)
    for (int i = t; i < 64 * 16; i += 256) {
        int r = i >> 4, c8 = (i & 15) << 3;
        if (r < rows) {
            const float* p = Cs + r * C_LD + c8;
            float4 a = *(const float4*)p;
            float4 b = *(const float4*)(p + 4);
            uint2 p0 = pack4_h(a);
            uint2 p1 = pack4_h(b);
            *(uint4*)(g_h + (size_t)(row0 + r) * D + c8) =
                make_uint4(p0.x, p0.y, p1.x, p1.y);
        }
    }
}

// ---------------- gather: warp per node, fp16 in/out, fused epilogue --------
__global__ void gather_kernel(const float* __restrict__ bias, int n, int do_pool) {
    int gwarp = (blockIdx.x * blockDim.x + threadIdx.x) >> 5;
    if (gwarp >= n) return;
    int lane = threadIdx.x & 31;
    int nd = gwarp;

    const uint2* hp = (const uint2*)g_h;
    float dv = g_dinv[nd];
    float d2 = dv * dv;

    float4 acc = make_float4(0.f, 0.f, 0.f, 0.f);
    fma4_h(acc, hp[(size_t)nd * 32 + lane], d2);

    int beg = g_off[nd];
    int end = g_off[nd + 1];
    int e = beg;
    for (; e + 3 < end; e += 4) {
        int2 r0 = __ldg(&g_csr[e]);
        int2 r1 = __ldg(&g_csr[e + 1]);
        int2 r2 = __ldg(&g_csr[e + 2]);
        int2 r3 = __ldg(&g_csr[e + 3]);
        uint2 v0 = hp[(size_t)r0.x * 32 + lane];
        uint2 v1 = hp[(size_t)r1.x * 32 + lane];
        uint2 v2 = hp[(size_t)r2.x * 32 + lane];
        uint2 v3 = hp[(size_t)r3.x * 32 + lane];
        fma4_h(acc, v0, __int_as_float(r0.y));
        fma4_h(acc, v1, __int_as_float(r1.y));
        fma4_h(acc, v2, __int_as_float(r2.y));
        fma4_h(acc, v3, __int_as_float(r3.y));
    }
    for (; e < end; e++) {
        int2 r = __ldg(&g_csr[e]);
        fma4_h(acc, hp[(size_t)r.x * 32 + lane], __int_as_float(r.y));
    }

    float4 bb = ((const float4*)bias)[lane];
    acc.x = fmaxf(acc.x + bb.x, 0.f);
    acc.y = fmaxf(acc.y + bb.y, 0.f);
    acc.z = fmaxf(acc.z + bb.z, 0.f);
    acc.w = fmaxf(acc.w + bb.w, 0.f);

    if (do_pool) {
        int g = g_batch[nd];
        red_add_v4(g_psum + (size_t)g * D + lane * 4, acc);
    } else {
        ((uint2*)g_acth)[(size_t)nd * 32 + lane] = pack4_h(acc);
    }
}

// ---------------- fused MLP head ---------------------------------------------
__global__ void fc_kernel(const float* __restrict__ Wfc, const float* __restrict__ bfc,
                          const float* __restrict__ Wfc2, const float* __restrict__ bfc2,
                          float* __restrict__ out) {
    __shared__ float p[D];
    __shared__ float h1[D_FF];
    int g = blockIdx.x;
    int t = threadIdx.x;

    int c = g_cnt[g]; if (c < 1) c = 1;
    float inv = 1.f / (float)c;
    if (t < D) p[t] = g_psum[g * D + t] * inv;
    __syncthreads();

    float s = bfc[t];
    #pragma unroll 4
    for (int k = 0; k < D; k++) s = fmaf(p[k], Wfc[k * D_FF + t], s);
    h1[t] = fmaxf(s, 0.f);
    __syncthreads();

    if (t < N_CLASSES) {
        float s2 = bfc2[t];
        #pragma unroll 4
        for (int k = 0; k < D_FF; k++) s2 = fmaf(h1[k], Wfc2[k * N_CLASSES + t], s2);
        out[g * N_CLASSES + t] = s2;
    }
}

// ---------------- launch -----------------------------------------------------
extern "C" void kernel_launch(void* const* d_in, const int* in_sizes, int n_in,
                              void* d_out, int out_size) {
    const float* x    = (const float*)d_in[0];
    const void*  ei   = d_in[1];
    const void*  batch= d_in[2];
    const float* W1   = (const float*)d_in[3];
    const float* b1   = (const float*)d_in[4];
    const float* W2   = (const float*)d_in[5];
    const float* b2   = (const float*)d_in[6];
    const float* W3   = (const float*)d_in[7];
    const float* b3   = (const float*)d_in[8];
    const float* Wfc  = (const float*)d_in[9];
    const float* bfc  = (const float*)d_in[10];
    const float* Wfc2 = (const float*)d_in[11];
    const float* bfc2 = (const float*)d_in[12];
    float* out = (float*)d_out;

    int n = in_sizes[0] / D;
    int E = in_sizes[1] / 2;

    const int GEMM_SMEM = (128 + 64) * AH_LD * 2;   // 52224 B
    static bool attr_set = false;
    if (!attr_set) {
        cudaFuncSetAttribute(gcn_gemm_tc16_kernel,
                             cudaFuncAttributeMaxDynamicSharedMemorySize, GEMM_SMEM);
        attr_set = true;
    }

    // ---- one-time setup ----
    detect_kernel<<<1, 32>>>((const int*)ei);
    init_kernel<<<(n + 255) / 256, 256>>>(n);
    convert_x_kernel<<<(n * 16 + 255) / 256, 256>>>(x, n);
    degree_kernel<<<2048, 256>>>(ei, E);
    int nb = (n + SCAN_BLK - 1) / SCAN_BLK;
    scanA_kernel<<<nb, 256>>>(n);
    scanB_kernel<<<1, 32>>>(nb, n);
    scanC_kernel<<<(n + 255) / 256, 256>>>(batch, n);
    fill_kernel<<<2048, 256>>>(ei, E);

    // ---- layers ----
    int gemm_blocks = (n + 63) / 64;
    int gather_blocks = (n * 32 + 255) / 256;

    gcn_gemm_tc16_kernel<<<gemm_blocks, 256, GEMM_SMEM>>>(W1, n);
    gather_kernel<<<gather_blocks, 256>>>(b1, n, 0);

    gcn_gemm_tc16_kernel<<<gemm_blocks, 256, GEMM_SMEM>>>(W2, n);
    gather_kernel<<<gather_blocks, 256>>>(b2, n, 0);

    gcn_gemm_tc16_kernel<<<gemm_blocks, 256, GEMM_SMEM>>>(W3, n);
    gather_kernel<<<gather_blocks, 256>>>(b3, n, 1);

    fc_kernel<<<N_GRAPHS, D_FF>>>(Wfc, bfc, Wfc2, bfc2, out);
}

// round 6
// speedup vs baseline: 2.5939x; 1.0982x over previous
#include <cuda_runtime.h>
#include <cuda_fp16.h>
#include <math.h>
#include <mma.h>

using namespace nvcuda;

#define N_NODES   100000
#define MAX_E     3300000
#define D         128
#define D_FF      256
#define N_CLASSES 26
#define N_GRAPHS  512
#define SCAN_BLK  1024

// ---------------- scratch (static __device__ — allocation-guard safe) -------
__device__ __half g_h   [(size_t)N_NODES * D];   // fp16 messages (GEMM out)
__device__ __half g_acth[(size_t)N_NODES * D];   // fp16 activations (GEMM in)
__device__ __half g_Wh  [3][D * D];              // preconverted fp16 weights
__device__ int    g_edeg[N_NODES];
__device__ float  g_dinv[N_NODES];
__device__ int    g_off [N_NODES + 1];
__device__ int    g_fill[N_NODES];
__device__ int    g_bsum[256];
__device__ int2   g_csr [MAX_E];                 // (src, weight-bits)
__device__ int    g_batch[N_NODES];
__device__ float  g_psum[N_GRAPHS * D];
__device__ int    g_cnt [N_GRAPHS];
__device__ int    g_is64;

// ---------------- helpers ---------------------------------------------------
__device__ __forceinline__ long long load_index(const void* p, long long pos, int is64) {
    if (is64) return ((const long long*)p)[pos];
    return (long long)((const int*)p)[pos];
}

__device__ __forceinline__ void red_add_v4(float* addr, float4 v) {
    asm volatile("red.global.add.v4.f32 [%0], {%1, %2, %3, %4};"
                 :: "l"(addr), "f"(v.x), "f"(v.y), "f"(v.z), "f"(v.w)
                 : "memory");
}

__device__ __forceinline__ void fma4_h(float4& acc, uint2 hv, float w) {
    __half2 h01 = *(__half2*)&hv.x;
    __half2 h23 = *(__half2*)&hv.y;
    float2 f01 = __half22float2(h01);
    float2 f23 = __half22float2(h23);
    acc.x = fmaf(w, f01.x, acc.x);
    acc.y = fmaf(w, f01.y, acc.y);
    acc.z = fmaf(w, f23.x, acc.z);
    acc.w = fmaf(w, f23.y, acc.w);
}

__device__ __forceinline__ uint2 pack4_h(float4 v) {
    __half2 a = __floats2half2_rn(v.x, v.y);
    __half2 b = __floats2half2_rn(v.z, v.w);
    uint2 r;
    r.x = *(unsigned*)&a;
    r.y = *(unsigned*)&b;
    return r;
}

// ---------------- setup kernels ---------------------------------------------
__global__ void detect_kernel(const int* ei) {
    if (blockIdx.x == 0 && threadIdx.x == 0) {
        int all0 = 1;
        #pragma unroll
        for (int i = 1; i < 64; i += 2) all0 &= (ei[i] == 0);
        g_is64 = all0;
    }
}

__global__ void init_kernel(int n) {
    int i = blockIdx.x * blockDim.x + threadIdx.x;
    if (i < n) g_edeg[i] = 0;
    if (i < N_GRAPHS * D) g_psum[i] = 0.f;
    if (i < N_GRAPHS) g_cnt[i] = 0;
}

// x (fp32) -> g_acth (fp16); 8 elems per thread
__global__ void convert_x_kernel(const float* __restrict__ x, int n) {
    long long i = blockIdx.x * (long long)blockDim.x + threadIdx.x;
    long long total = (long long)n * 16;
    if (i < total) {
        float4 a = ((const float4*)x)[i * 2];
        float4 b = ((const float4*)x)[i * 2 + 1];
        uint2 p0 = pack4_h(a);
        uint2 p1 = pack4_h(b);
        ((uint4*)g_acth)[i] = make_uint4(p0.x, p0.y, p1.x, p1.y);
    }
}

// W1/W2/W3 (fp32) -> g_Wh (fp16); 4 elems per thread, 3*4096 threads
__global__ void convW_kernel(const float* __restrict__ W1,
                             const float* __restrict__ W2,
                             const float* __restrict__ W3) {
    int i = blockIdx.x * blockDim.x + threadIdx.x;
    if (i < 3 * 4096) {
        int sel = i >> 12, j = i & 4095;
        const float* W = sel == 0 ? W1 : (sel == 1 ? W2 : W3);
        float4 w = ((const float4*)W)[j];
        ((uint2*)g_Wh[sel])[j] = pack4_h(w);
    }
}

__global__ void degree_kernel(const void* ei, int E) {
    int is64 = g_is64;
    for (long long e = blockIdx.x * (long long)blockDim.x + threadIdx.x;
         e < E; e += (long long)gridDim.x * blockDim.x) {
        long long d = load_index(ei, (long long)E + e, is64);
        atomicAdd(&g_edeg[d], 1);
    }
}

__global__ void scanA_kernel(int n) {
    __shared__ int ssum[256];
    int b = blockIdx.x, t = threadIdx.x;
    int base = b * SCAN_BLK + t * 4;
    int v[4];
    #pragma unroll
    for (int j = 0; j < 4; j++) {
        int idx = base + j;
        v[j] = (idx < n) ? g_edeg[idx] : 0;
        if (idx < n) g_dinv[idx] = rsqrtf((float)(v[j] + 1));
    }
    int tot = v[0] + v[1] + v[2] + v[3];
    ssum[t] = tot;
    __syncthreads();
    #pragma unroll
    for (int ofs = 1; ofs < 256; ofs <<= 1) {
        int val = (t >= ofs) ? ssum[t - ofs] : 0;
        __syncthreads();
        ssum[t] += val;
        __syncthreads();
    }
    int excl = ssum[t] - tot;
    int run = excl;
    #pragma unroll
    for (int j = 0; j < 4; j++) {
        int idx = base + j;
        if (idx < n) g_off[idx] = run;
        run += v[j];
    }
    if (t == 255) g_bsum[b] = ssum[255];
}

__global__ void scanB_kernel(int nb, int n) {
    if (threadIdx.x == 0 && blockIdx.x == 0) {
        int run = 0;
        for (int b = 0; b < nb; b++) {
            int t = g_bsum[b];
            g_bsum[b] = run;
            run += t;
        }
        g_off[n] = run;
    }
}

__global__ void scanC_kernel(const void* batch, int n) {
    int i = blockIdx.x * blockDim.x + threadIdx.x;
    if (i < n) {
        int o = g_off[i] + g_bsum[i / SCAN_BLK];
        g_off[i] = o;
        g_fill[i] = o;
        int g = (int)load_index(batch, i, g_is64);
        g_batch[i] = g;
        atomicAdd(&g_cnt[g], 1);
    }
}

__global__ void fill_kernel(const void* ei, int E) {
    int is64 = g_is64;
    for (long long e = blockIdx.x * (long long)blockDim.x + threadIdx.x;
         e < E; e += (long long)gridDim.x * blockDim.x) {
        long long s = load_index(ei, e, is64);
        long long d = load_index(ei, (long long)E + e, is64);
        int pos = atomicAdd(&g_fill[d], 1);
        float w = g_dinv[s] * g_dinv[d];
        g_csr[pos] = make_int2((int)s, __float_as_int(w));
    }
}

// ---------------- fp16 tensor-core GEMM: g_h = g_acth @ g_Wh[layer] ----------
// Block: 64 rows x 128 cols, 256 threads = 8 warps (4 row-groups x 2 col-groups).
#define AH_LD 136
#define C_LD  132
__global__ void gcn_gemm_tc16_kernel(int layer, int n) {
    extern __shared__ char smc[];
    __half* Ws = (__half*)smc;                   // 128 x AH_LD
    __half* As = Ws + 128 * AH_LD;               // 64 x AH_LD
    float*  Cs = (float*)smc;                    // 64 x C_LD (epilogue)

    const __half* Wh = g_Wh[layer];
    int row0 = blockIdx.x * 64;
    int t = threadIdx.x;
    int rows = n - row0; if (rows > 64) rows = 64;

    // load W (fp16, 8 halves = 16B per op)
    for (int i = t; i < 128 * 16; i += 256) {
        int r = i >> 4, c8 = (i & 15) << 3;
        *(uint4*)(Ws + r * AH_LD + c8) = *(const uint4*)(Wh + r * D + c8);
    }
    // load A tile
    for (int i = t; i < 64 * 16; i += 256) {
        int r = i >> 4, c8 = (i & 15) << 3;
        uint4 v;
        if (r < rows)
            v = *(const uint4*)(g_acth + (size_t)(row0 + r) * D + c8);
        else
            v = make_uint4(0, 0, 0, 0);
        *(uint4*)(As + r * AH_LD + c8) = v;
    }
    __syncthreads();

    int warp = t >> 5;
    int wrow = warp & 3;
    int wcol = warp >> 2;

    wmma::fragment<wmma::accumulator, 16, 16, 16, float> acc[4];
    #pragma unroll
    for (int j = 0; j < 4; j++) wmma::fill_fragment(acc[j], 0.f);

    const __half* arow = As + wrow * 16 * AH_LD;
    #pragma unroll
    for (int k0 = 0; k0 < 128; k0 += 16) {
        wmma::fragment<wmma::matrix_a, 16, 16, 16, __half, wmma::row_major> af;
        wmma::load_matrix_sync(af, arow + k0, AH_LD);
        #pragma unroll
        for (int nc = 0; nc < 4; nc++) {
            int ncol = wcol * 64 + nc * 16;
            wmma::fragment<wmma::matrix_b, 16, 16, 16, __half, wmma::row_major> bf;
            wmma::load_matrix_sync(bf, Ws + k0 * AH_LD + ncol, AH_LD);
            wmma::mma_sync(acc[nc], af, bf, acc[nc]);
        }
    }
    __syncthreads();

    #pragma unroll
    for (int nc = 0; nc < 4; nc++) {
        int ncol = wcol * 64 + nc * 16;
        wmma::store_matrix_sync(Cs + wrow * 16 * C_LD + ncol, acc[nc], C_LD,
                                wmma::mem_row_major);
    }
    __syncthreads();

    for (int i = t; i < 64 * 16; i += 256) {
        int r = i >> 4, c8 = (i & 15) << 3;
        if (r < rows) {
            const float* p = Cs + r * C_LD + c8;
            float4 a = *(const float4*)p;
            float4 b = *(const float4*)(p + 4);
            uint2 p0 = pack4_h(a);
            uint2 p1 = pack4_h(b);
            *(uint4*)(g_h + (size_t)(row0 + r) * D + c8) =
                make_uint4(p0.x, p0.y, p1.x, p1.y);
        }
    }
}

// ---------------- gather: warp per node, fp16 in/out, fused epilogue --------
__global__ void gather_kernel(const float* __restrict__ bias, int n, int do_pool) {
    int gwarp = (blockIdx.x * blockDim.x + threadIdx.x) >> 5;
    if (gwarp >= n) return;
    int lane = threadIdx.x & 31;
    int nd = gwarp;

    const uint2* hp = (const uint2*)g_h;
    float dv = g_dinv[nd];
    float d2 = dv * dv;

    float4 acc = make_float4(0.f, 0.f, 0.f, 0.f);
    fma4_h(acc, hp[(size_t)nd * 32 + lane], d2);

    int beg = g_off[nd];
    int end = g_off[nd + 1];
    int e = beg;
    for (; e + 3 < end; e += 4) {
        int2 r0 = __ldg(&g_csr[e]);
        int2 r1 = __ldg(&g_csr[e + 1]);
        int2 r2 = __ldg(&g_csr[e + 2]);
        int2 r3 = __ldg(&g_csr[e + 3]);
        uint2 v0 = hp[(size_t)r0.x * 32 + lane];
        uint2 v1 = hp[(size_t)r1.x * 32 + lane];
        uint2 v2 = hp[(size_t)r2.x * 32 + lane];
        uint2 v3 = hp[(size_t)r3.x * 32 + lane];
        fma4_h(acc, v0, __int_as_float(r0.y));
        fma4_h(acc, v1, __int_as_float(r1.y));
        fma4_h(acc, v2, __int_as_float(r2.y));
        fma4_h(acc, v3, __int_as_float(r3.y));
    }
    for (; e < end; e++) {
        int2 r = __ldg(&g_csr[e]);
        fma4_h(acc, hp[(size_t)r.x * 32 + lane], __int_as_float(r.y));
    }

    float4 bb = ((const float4*)bias)[lane];
    acc.x = fmaxf(acc.x + bb.x, 0.f);
    acc.y = fmaxf(acc.y + bb.y, 0.f);
    acc.z = fmaxf(acc.z + bb.z, 0.f);
    acc.w = fmaxf(acc.w + bb.w, 0.f);

    if (do_pool) {
        int g = g_batch[nd];
        red_add_v4(g_psum + (size_t)g * D + lane * 4, acc);
    } else {
        ((uint2*)g_acth)[(size_t)nd * 32 + lane] = pack4_h(acc);
    }
}

// ---------------- fused MLP head ---------------------------------------------
__global__ void fc_kernel(const float* __restrict__ Wfc, const float* __restrict__ bfc,
                          const float* __restrict__ Wfc2, const float* __restrict__ bfc2,
                          float* __restrict__ out) {
    __shared__ float p[D];
    __shared__ float h1[D_FF];
    int g = blockIdx.x;
    int t = threadIdx.x;

    int c = g_cnt[g]; if (c < 1) c = 1;
    float inv = 1.f / (float)c;
    if (t < D) p[t] = g_psum[g * D + t] * inv;
    __syncthreads();

    float s = bfc[t];
    #pragma unroll 4
    for (int k = 0; k < D; k++) s = fmaf(p[k], Wfc[k * D_FF + t], s);
    h1[t] = fmaxf(s, 0.f);
    __syncthreads();

    if (t < N_CLASSES) {
        float s2 = bfc2[t];
        #pragma unroll 4
        for (int k = 0; k < D_FF; k++) s2 = fmaf(h1[k], Wfc2[k * N_CLASSES + t], s2);
        out[g * N_CLASSES + t] = s2;
    }
}

// ---------------- launch -----------------------------------------------------
extern "C" void kernel_launch(void* const* d_in, const int* in_sizes, int n_in,
                              void* d_out, int out_size) {
    const float* x    = (const float*)d_in[0];
    const void*  ei   = d_in[1];
    const void*  batch= d_in[2];
    const float* W1   = (const float*)d_in[3];
    const float* b1   = (const float*)d_in[4];
    const float* W2   = (const float*)d_in[5];
    const float* b2   = (const float*)d_in[6];
    const float* W3   = (const float*)d_in[7];
    const float* b3   = (const float*)d_in[8];
    const float* Wfc  = (const float*)d_in[9];
    const float* bfc  = (const float*)d_in[10];
    const float* Wfc2 = (const float*)d_in[11];
    const float* bfc2 = (const float*)d_in[12];
    float* out = (float*)d_out;

    int n = in_sizes[0] / D;
    int E = in_sizes[1] / 2;

    const int GEMM_SMEM = (128 + 64) * AH_LD * 2;   // 52224 B

    static bool once_done = false;
    static cudaStream_t s1;
    static cudaEvent_t ev_fork, ev_join;
    if (!once_done) {
        cudaFuncSetAttribute(gcn_gemm_tc16_kernel,
                             cudaFuncAttributeMaxDynamicSharedMemorySize, GEMM_SMEM);
        cudaStreamCreateWithFlags(&s1, cudaStreamNonBlocking);
        cudaEventCreateWithFlags(&ev_fork, cudaEventDisableTiming);
        cudaEventCreateWithFlags(&ev_join, cudaEventDisableTiming);
        once_done = true;
    }

    int gemm_blocks = (n + 63) / 64;
    int gather_blocks = (n * 32 + 255) / 256;
    int nb = (n + SCAN_BLK - 1) / SCAN_BLK;

    // ---- fork: feature path on s1, graph-structure path on capture stream ----
    detect_kernel<<<1, 32>>>((const int*)ei);
    init_kernel<<<(n + 255) / 256, 256>>>(n);
    cudaEventRecord(ev_fork, 0);
    cudaStreamWaitEvent(s1, ev_fork, 0);

    // s1: x->fp16, W->fp16, layer-1 GEMM (needs no graph structure)
    convert_x_kernel<<<(n * 16 + 255) / 256, 256, 0, s1>>>(x, n);
    convW_kernel<<<(3 * 4096 + 255) / 256, 256, 0, s1>>>(W1, W2, W3);
    gcn_gemm_tc16_kernel<<<gemm_blocks, 256, GEMM_SMEM, s1>>>(0, n);
    cudaEventRecord(ev_join, s1);

    // capture stream: degree -> scan -> CSR fill
    degree_kernel<<<2048, 256>>>(ei, E);
    scanA_kernel<<<nb, 256>>>(n);
    scanB_kernel<<<1, 32>>>(nb, n);
    scanC_kernel<<<(n + 255) / 256, 256>>>(batch, n);
    fill_kernel<<<2048, 256>>>(ei, E);
    cudaStreamWaitEvent(0, ev_join, 0);

    // ---- layers (sequential from here) ----
    gather_kernel<<<gather_blocks, 256>>>(b1, n, 0);

    gcn_gemm_tc16_kernel<<<gemm_blocks, 256, GEMM_SMEM>>>(1, n);
    gather_kernel<<<gather_blocks, 256>>>(b2, n, 0);

    gcn_gemm_tc16_kernel<<<gemm_blocks, 256, GEMM_SMEM>>>(2, n);
    gather_kernel<<<gather_blocks, 256>>>(b3, n, 1);

    fc_kernel<<<N_GRAPHS, D_FF>>>(Wfc, bfc, Wfc2, bfc2, out);
}